// round 16
// baseline (speedup 1.0000x reference)
#include <cuda_runtime.h>

// LSTM seq2seq: encoder (1->64) over T=1000, decoder (1->65) with teacher
// forcing over T=1000, output Linear(65->1). B=2048.
//
// Round 16 = round 15 with the weight-tile indexing bug FIXED:
// w2[r*16 + p], p in 0..15 (16 col-pairs = 32 cols per row). Round 15
// loaded only 8 pairs/row at stride 8 and the MMA loop read past them
// (uninitialized regs -> NaN).
//
// Design: 1 CTA/SM (148 CTAs x 256 threads, bt=13/14), 255-reg budget.
// Threads split in 2 groups of 128; group g owns batch rows [7g, ...).
// Thread = (quad q, half): gate rows {4q..4q+3} x cols [32*half,+32)
// -> 128 weight regs, each LDS.128 feeds 8 FFMA2 (2x reuse of round 4).
// Combine: 2 shfl per 4 rows; thread finalizes 2 rows, applies activation
// (sigmoid / tanh-for-g), swizzled STS. Update: c in regs, activated-gate
// LDS.128 + rotate-select, tanh(cn) only.

#define T_STEPS   1000
#define BATCH     2048
#define NCTA      148
#define NTHREADS  256
#define BT_MAX    14
#define HP        72     // h row pitch; cols0-31 at +0, cols32-63 at +36, col64 at +68
#define GP        264    // gates row pitch (66 float4 slots; unit j at slot j)

typedef unsigned long long u64;

struct Smem {
    float h[BT_MAX * HP];      // split layout
    float c[BT_MAX * HP];      // linear; init + enc->dec transition only
    float gates[BT_MAX * GP];  // ACTIVATED gates, swizzled slots
    float xbuf[2][BT_MAX + 2];
    float xw[4 * 68];          // decoder gate rows 256..259 (65 weights)
    float xwih[4];
    float xbias[4];
    float linW[68];
};

__device__ __forceinline__ u64 pack2(float lo, float hi) {
    u64 r;
    asm("mov.b64 %0, {%1, %2};" : "=l"(r) : "f"(lo), "f"(hi));
    return r;
}
__device__ __forceinline__ float2 unpack2(u64 v) {
    float lo, hi;
    asm("mov.b64 {%0, %1}, %2;" : "=f"(lo), "=f"(hi) : "l"(v));
    return make_float2(lo, hi);
}
__device__ __forceinline__ void ffma2(u64& d, u64 a, u64 b, u64 c) {
    asm("fma.rn.f32x2 %0, %1, %2, %3;" : "=l"(d) : "l"(a), "l"(b), "l"(c));
}
__device__ __forceinline__ float sigf(float x) {
    return __fdividef(1.0f, 1.0f + __expf(-x));
}
__device__ __forceinline__ float tanh_s(float x) {
    return fmaf(2.0f, sigf(x + x), -1.0f);
}
__device__ __forceinline__ float act(float x, bool isg) {
    float y = isg ? (x + x) : x;
    float a = sigf(y);
    return isg ? fmaf(2.0f, a, -1.0f) : a;
}
// swizzled gate slot for row (gate, j): float index 4j + ((gate + (j>>3)) & 3)
__device__ __forceinline__ int gate_off(int gate, int j) {
    return 4 * j + ((gate + ((j >> 3) & 3)) & 3);
}

// Gate block: NB batch rows (absolute start babs). Thread holds 4 rows x
// 32 cols (its k-half): w2[r*16+p] = col-pair p (0..15) of row 4q+r.
template <int H, int NB>
__device__ __forceinline__ void gate_block(
    Smem& sm, const float* xs, int babs,
    const u64* w2, int half,
    float bias_a, float wih_a, float w64a, int goff_a, bool isg_a,
    float bias_b, float wih_b, float w64b, int goff_b, bool isg_b)
{
    u64 acc[NB][4];
    const ulonglong2* hp[NB];
    float h64[NB];
#pragma unroll
    for (int u = 0; u < NB; u++) {
        acc[u][0] = acc[u][1] = acc[u][2] = acc[u][3] = 0ull;
        hp[u] = (const ulonglong2*)(sm.h + (babs + u) * HP + half * 36);
        if constexpr (H == 65) h64[u] = sm.h[(babs + u) * HP + 68];
    }
#pragma unroll
    for (int qq = 0; qq < 8; qq++) {
#pragma unroll
        for (int u = 0; u < NB; u++) {
            ulonglong2 h2 = hp[u][qq];   // 2 disjoint-bank broadcast groups
#pragma unroll
            for (int r = 0; r < 4; r++) {
                ffma2(acc[u][r], w2[r * 16 + 2 * qq],     h2.x, acc[u][r]);
                ffma2(acc[u][r], w2[r * 16 + 2 * qq + 1], h2.y, acc[u][r]);
            }
        }
    }
#pragma unroll
    for (int u = 0; u < NB; u++) {
        float2 v0 = unpack2(acc[u][0]);
        float2 v1 = unpack2(acc[u][1]);
        float2 v2 = unpack2(acc[u][2]);
        float2 v3 = unpack2(acc[u][3]);
        const float p0 = v0.x + v0.y;
        const float p1 = v1.x + v1.y;
        const float p2 = v2.x + v2.y;
        const float p3 = v3.x + v3.y;
        // exchange with k-half partner: half=0 finalizes rows 4q,4q+1;
        // half=1 finalizes rows 4q+2,4q+3
        const float r1 = __shfl_xor_sync(0xffffffffu, half ? p0 : p2, 1);
        const float r2 = __shfl_xor_sync(0xffffffffu, half ? p1 : p3, 1);
        float fa = (half ? p2 : p0) + r1;
        float fb = (half ? p3 : p1) + r2;
        const float x = xs[babs + u];
        fa += bias_a + wih_a * x;
        fb += bias_b + wih_b * x;
        if constexpr (H == 65) {
            fa = fmaf(w64a, h64[u], fa);
            fb = fmaf(w64b, h64[u], fb);
        }
        sm.gates[(babs + u) * GP + goff_a] = act(fa, isg_a);
        sm.gates[(babs + u) * GP + goff_b] = act(fb, isg_b);
    }
}

template <int H, bool IS_DEC, int BTN>
__device__ void lstm_scan(
    Smem& sm, int b0,
    const float* __restrict__ xglob,
    const float* __restrict__ Wih,
    const float* __restrict__ Whh,
    const float* __restrict__ bih,
    const float* __restrict__ bhh,
    float* __restrict__ out,
    float linb)
{
    const int tid  = threadIdx.x;
    const int wid  = tid >> 5;
    const int lane = tid & 31;
    const int grp  = tid >> 7;          // batch group (warps 0-3 / 4-7)
    const int gu   = tid & 127;
    const int q4   = gu >> 1;           // row quad 0..63
    const int half = gu & 1;
    const int bofs = grp * 7;
    const int bcnt = grp ? (BTN - 7) : 7;

    // ---- weight tile: rows {4q..4q+3}, cols [32*half, +32) -> 64 u64 ----
    u64 w2[64];
#pragma unroll
    for (int r = 0; r < 4; r++) {
        const float* wr = Whh + (4 * q4 + r) * H + half * 32;
#pragma unroll
        for (int p = 0; p < 16; p++)
            w2[r * 16 + p] = pack2(wr[2 * p], wr[2 * p + 1]);
    }
    // finalized rows ra = 4q + 2*half, rb = ra+1
    const int ra = 4 * q4 + 2 * half;
    const int rb = ra + 1;
    const int ga_g = (H == 64) ? (ra >> 6) : (ra / 65);
    const int ga_j = (H == 64) ? (ra & 63) : (ra - ga_g * 65);
    const int gb_g = (H == 64) ? (rb >> 6) : (rb / 65);
    const int gb_j = (H == 64) ? (rb & 63) : (rb - gb_g * 65);
    const int  goff_a = gate_off(ga_g, ga_j);
    const int  goff_b = gate_off(gb_g, gb_j);
    const bool isg_a = (ga_g == 2), isg_b = (gb_g == 2);
    const float bias_a = bih[ra] + bhh[ra], wih_a = Wih[ra];
    const float bias_b = bih[rb] + bhh[rb], wih_b = Wih[rb];
    const float w64a = (H == 65) ? Whh[ra * H + 64] : 0.0f;
    const float w64b = (H == 65) ? Whh[rb * H + 64] : 0.0f;

    // ---- update mapping (loop-invariant), c in registers ----
    int ucnt = 0;
    int ub[4], ujj[4], uha[4], urot[4];
    float cr[4];
    {
        const int npairs = H * BTN;
        for (int p = tid; p < npairs; p += NTHREADS) {
            const int b = p / H;
            const int j = p - b * H;
            ub[ucnt]   = b;
            ujj[ucnt]  = j;
            uha[ucnt]  = b * HP + ((j < 32) ? j : (j < 64) ? (j + 4) : 68);
            urot[ucnt] = (j >> 3) & 3;
            cr[ucnt]   = sm.c[b * HP + j];
            ucnt++;
        }
    }

    // ---- decoder hoists ----
    float lw0 = 0.f, lw1 = 0.f, lw64 = 0.f;
    if constexpr (IS_DEC) {
        lw0  = sm.linW[lane];
        lw1  = sm.linW[lane + 32];
        lw64 = sm.linW[64];
    }

    for (int t = 0; t < T_STEPS; t++) {
        float xnext = 0.0f;
        const bool do_pref = (tid < BTN) && (t + 1 < T_STEPS);
        if (do_pref) {
            const int row = IS_DEC ? t : (t + 1);
            xnext = xglob[row * BATCH + b0 + tid];
        }
        const float* xs = sm.xbuf[t & 1];

        // ---- gate phase: this group's batch rows ----
        {
            int b = 0;
            for (; b + 4 <= bcnt; b += 4)
                gate_block<H, 4>(sm, xs, bofs + b, w2, half,
                                 bias_a, wih_a, w64a, goff_a, isg_a,
                                 bias_b, wih_b, w64b, goff_b, isg_b);
            const int rem = bcnt - b;
            if (rem == 3)      gate_block<H, 3>(sm, xs, bofs + b, w2, half,
                                 bias_a, wih_a, w64a, goff_a, isg_a,
                                 bias_b, wih_b, w64b, goff_b, isg_b);
            else if (rem == 2) gate_block<H, 2>(sm, xs, bofs + b, w2, half,
                                 bias_a, wih_a, w64a, goff_a, isg_a,
                                 bias_b, wih_b, w64b, goff_b, isg_b);
            else if (rem == 1) gate_block<H, 1>(sm, xs, bofs + b, w2, half,
                                 bias_a, wih_a, w64a, goff_a, isg_a,
                                 bias_b, wih_b, w64b, goff_b, isg_b);
        }

        // ---- decoder: leftover rows 256..259 (o-gates, units 61..64) ----
        if constexpr (IS_DEC) {
            for (int task = wid; task < 4 * BTN; task += 8) {
                const int e = task & 3;
                const int b = task >> 2;
                const float* w    = sm.xw + e * 68;
                const float* hrow = sm.h + b * HP;
                float p = w[lane] * hrow[lane] + w[lane + 32] * hrow[36 + lane];
                if (lane == 0) p += w[64] * hrow[68];
#pragma unroll
                for (int off = 16; off; off >>= 1)
                    p += __shfl_down_sync(0xffffffffu, p, off);
                if (lane == 0)
                    sm.gates[b * GP + gate_off(3, 61 + e)] =
                        sigf(sm.xbias[e] + sm.xwih[e] * xs[b] + p);
            }
        }

        if (do_pref) sm.xbuf[(t + 1) & 1][tid] = xnext;
        __syncthreads();

        // ---- pointwise update: activated gates, tanh(cn) only ----
#pragma unroll
        for (int k = 0; k < 4; k++) {
            if (k < ucnt) {
                const float4 g4 = ((const float4*)(sm.gates + ub[k] * GP))[ujj[k]];
                const int rot = urot[k];
                const bool s1 = rot & 1, s2 = rot & 2;
                const float t0 = s1 ? g4.y : g4.x;
                const float t1 = s1 ? g4.z : g4.y;
                const float t2 = s1 ? g4.w : g4.z;
                const float t3 = s1 ? g4.x : g4.w;
                const float ai = s2 ? t2 : t0;
                const float af = s2 ? t3 : t1;
                const float ag = s2 ? t0 : t2;
                const float ao = s2 ? t1 : t3;
                const float cn = af * cr[k] + ai * ag;
                cr[k] = cn;
                sm.h[uha[k]] = ao * tanh_s(cn);
            }
        }
        __syncthreads();

        // ---- decoder: output projection ----
        if constexpr (IS_DEC) {
            for (int b = wid; b < BTN; b += 8) {
                const float* hrow = sm.h + b * HP;
                float p = lw0 * hrow[lane] + lw1 * hrow[36 + lane];
                if (lane == 0) p += lw64 * hrow[68];
#pragma unroll
                for (int off = 16; off; off >>= 1)
                    p += __shfl_down_sync(0xffffffffu, p, off);
                if (lane == 0)
                    out[t * BATCH + b0 + b] = p + linb;
            }
        }
    }

    // ---- write c back (needed for the enc->dec transition remap) ----
    if constexpr (!IS_DEC) {
#pragma unroll
        for (int k = 0; k < 4; k++)
            if (k < ucnt) sm.c[ub[k] * HP + ujj[k]] = cr[k];
    }
}

template <int BTN>
__device__ void body(
    Smem& sm, int b0,
    const float* input, const float* speed, const float* target,
    const float* eWih, const float* eWhh, const float* ebih, const float* ebhh,
    const float* dWih, const float* dWhh, const float* dbih, const float* dbhh,
    const float* linW, const float* linb, const float* denseW, const float* denseb,
    float* out)
{
    const int tid = threadIdx.x;

    // encoder scan (H=64)
    lstm_scan<64, false, BTN>(sm, b0, input, eWih, eWhh, ebih, ebhh, nullptr, 0.0f);
    __syncthreads();

    // transition: append Dense(speed); x_dec[0] = 0
    if (tid < BTN) {
        const float sp = denseb[0] + denseW[0] * speed[b0 + tid];
        sm.h[tid * HP + 68] = sp;      // h split layout: col 64 at +68
        sm.c[tid * HP + 64] = sp;      // c linear
        sm.xbuf[0][tid] = 0.0f;
    }
    __syncthreads();

    // decoder scan (H=65) + output projection
    lstm_scan<65, true, BTN>(sm, b0, target, dWih, dWhh, dbih, dbhh, out, linb[0]);
}

__global__ void __launch_bounds__(NTHREADS, 1)
lstm_seq2seq_kernel(
    const float* __restrict__ input,  const float* __restrict__ speed,
    const float* __restrict__ target,
    const float* __restrict__ eWih,   const float* __restrict__ eWhh,
    const float* __restrict__ ebih,   const float* __restrict__ ebhh,
    const float* __restrict__ dWih,   const float* __restrict__ dWhh,
    const float* __restrict__ dbih,   const float* __restrict__ dbhh,
    const float* __restrict__ linW,   const float* __restrict__ linb,
    const float* __restrict__ denseW, const float* __restrict__ denseb,
    float* __restrict__ out)
{
    __shared__ Smem sm;
    const int tid  = threadIdx.x;
    const int cta  = blockIdx.x;
    const int base = BATCH / NCTA;     // 13
    const int rem  = BATCH % NCTA;     // 124
    const int bt   = base + (cta < rem ? 1 : 0);
    const int b0   = cta * base + min(cta, rem);

    for (int i = tid; i < BT_MAX * HP; i += NTHREADS) {
        sm.h[i] = 0.0f;
        sm.c[i] = 0.0f;
    }
    for (int i = tid; i < 4 * 65; i += NTHREADS) {
        const int e = i / 65, k = i - e * 65;
        sm.xw[e * 68 + k] = dWhh[(256 + e) * 65 + k];
    }
    if (tid < 4) {
        sm.xwih[tid]  = dWih[256 + tid];
        sm.xbias[tid] = dbih[256 + tid] + dbhh[256 + tid];
    }
    for (int i = tid; i < 65; i += NTHREADS) sm.linW[i] = linW[i];
    if (tid < bt) sm.xbuf[0][tid] = input[b0 + tid];
    __syncthreads();

    if (bt == 14)
        body<14>(sm, b0, input, speed, target, eWih, eWhh, ebih, ebhh,
                 dWih, dWhh, dbih, dbhh, linW, linb, denseW, denseb, out);
    else
        body<13>(sm, b0, input, speed, target, eWih, eWhh, ebih, ebhh,
                 dWih, dWhh, dbih, dbhh, linW, linb, denseW, denseb, out);
}

extern "C" void kernel_launch(void* const* d_in, const int* in_sizes, int n_in,
                              void* d_out, int out_size)
{
    const float* input  = (const float*)d_in[0];
    const float* speed  = (const float*)d_in[1];
    const float* target = (const float*)d_in[2];
    const float* eWih   = (const float*)d_in[3];
    const float* eWhh   = (const float*)d_in[4];
    const float* ebih   = (const float*)d_in[5];
    const float* ebhh   = (const float*)d_in[6];
    const float* dWih   = (const float*)d_in[7];
    const float* dWhh   = (const float*)d_in[8];
    const float* dbih   = (const float*)d_in[9];
    const float* dbhh   = (const float*)d_in[10];
    const float* linW   = (const float*)d_in[11];
    const float* linb   = (const float*)d_in[12];
    const float* denseW = (const float*)d_in[13];
    const float* denseb = (const float*)d_in[14];
    float* out = (float*)d_out;

    lstm_seq2seq_kernel<<<NCTA, NTHREADS>>>(
        input, speed, target,
        eWih, eWhh, ebih, ebhh,
        dWih, dWhh, dbih, dbhh,
        linW, linb, denseW, denseb, out);
}

// round 17
// speedup vs baseline: 1.0254x; 1.0254x over previous
#include <cuda_runtime.h>

// LSTM seq2seq: encoder (1->64) over T=1000, decoder (1->65) with teacher
// forcing over T=1000, output Linear(65->1). B=2048.
//
// Round 17: fused full-width design, ONE barrier per step, no gates smem.
// 1 CTA x 256 threads (148 CTAs, bt=13/14, ~180 regs). 2 groups x 128
// threads; group owns 7 batch rows. Thread owns 2 FULL-WIDTH gate rows of
// ONE unit u: lane<16 -> {i,f}, lane>=16 -> {g,o} (partner lane^16).
// Per batch row: 16 broadcast LDS.128 -> 64 FFMA2 (4 chains) -> act ->
// one shfl_xor(16) pair -> i,f-thread updates c (regs) and writes h to the
// double-buffered next state. Decoder unit 64 + projection: warp-coop
// tasks striped over the group's warps, reading stable h[t-1].

#define T_STEPS  1000
#define BATCH    2048
#define NCTA     148
#define NTHREADS 256
#define BT_MAX   14
#define HP       68     // h row pitch (floats), linear, col 64 at +64

typedef unsigned long long u64;

struct __align__(16) Smem {
    float h[2][BT_MAX * HP];
    float xbuf[2][BT_MAX + 2];
    float xw[4][68];     // decoder unit-64 gate rows {65e+64} (65 weights)
    float xwih[4];
    float xbias[4];
    float linW[68];
};

__device__ __forceinline__ u64 pack2(float lo, float hi) {
    u64 r;
    asm("mov.b64 %0, {%1, %2};" : "=l"(r) : "f"(lo), "f"(hi));
    return r;
}
__device__ __forceinline__ float2 unpack2(u64 v) {
    float lo, hi;
    asm("mov.b64 {%0, %1}, %2;" : "=f"(lo), "=f"(hi) : "l"(v));
    return make_float2(lo, hi);
}
__device__ __forceinline__ void ffma2(u64& d, u64 a, u64 b, u64 c) {
    asm("fma.rn.f32x2 %0, %1, %2, %3;" : "=l"(d) : "l"(a), "l"(b), "l"(c));
}
__device__ __forceinline__ float sigf(float x) {
    return __fdividef(1.0f, 1.0f + __expf(-x));
}
__device__ __forceinline__ float tanh_s(float x) {
    return fmaf(2.0f, sigf(x + x), -1.0f);
}
__device__ __forceinline__ float act(float x, bool isg) {
    float y = isg ? (x + x) : x;
    float a = sigf(y);
    return isg ? fmaf(2.0f, a, -1.0f) : a;
}

template <int H, bool DEC, int BTN>
__device__ void lstm_scan(
    Smem& sm, int b0,
    const float* __restrict__ xg,
    const float* __restrict__ Wih, const float* __restrict__ Whh,
    const float* __restrict__ bih, const float* __restrict__ bhh,
    float* c,                       // 7 cell regs (used by i,f-threads)
    float linb, float* __restrict__ out)
{
    const int tid  = threadIdx.x;
    const int lane = tid & 31;
    const int grp  = tid >> 7;          // batch group
    const int w4   = (tid >> 5) & 3;    // warp within group
    const bool isA = (lane < 16);       // A: {i,f} rows; B: {g,o} rows
    const int u    = w4 * 16 + (lane & 15);   // hidden unit 0..63
    const int bofs = grp * 7;
    const int bcnt = grp ? (BTN - 7) : 7;

    // ---- weights: 2 full-width rows (r0, r0+H) -> 64 u64 regs ----
    const int r0 = isA ? u : (2 * H + u);
    const int r1 = r0 + H;
    u64 wa[32], wb[32];
    float wrem_a = 0.f, wrem_b = 0.f;
    {
        const float* p0 = Whh + r0 * H;
        const float* p1 = Whh + r1 * H;
#pragma unroll
        for (int q = 0; q < 32; q++) {
            wa[q] = pack2(p0[2 * q], p0[2 * q + 1]);
            wb[q] = pack2(p1[2 * q], p1[2 * q + 1]);
        }
        if constexpr (H == 65) { wrem_a = p0[64]; wrem_b = p1[64]; }
    }
    const float wih0  = Wih[r0], wih1 = Wih[r1];
    const float bias0 = bih[r0] + bhh[r0];
    const float bias1 = bih[r1] + bhh[r1];

    // ---- decoder task hoists (unit-64 gates + projection) ----
    float te0[4], te1[4], te64[4];
    float lw0 = 0.f, lw1 = 0.f, lw64 = 0.f;
    float c64r[2];
    if constexpr (DEC) {
#pragma unroll
        for (int e = 0; e < 4; e++) {
            te0[e]  = sm.xw[e][lane];
            te1[e]  = sm.xw[e][lane + 32];
            te64[e] = sm.xw[e][64];
        }
        lw0 = sm.linW[lane]; lw1 = sm.linW[lane + 32]; lw64 = sm.linW[64];
        // c64 init == h64 init == Dense(speed), staged in h[0] col 64
#pragma unroll
        for (int k = 0; k < 2; k++) {
            const int b = w4 + 4 * k;
            c64r[k] = (b < bcnt) ? sm.h[0][(bofs + b) * HP + 64] : 0.f;
        }
    }

    int cur = 0;
    for (int t = 0; t < T_STEPS; t++) {
        const float* hc = sm.h[cur];
        float* hn = sm.h[cur ^ 1];
        const float* xs = sm.xbuf[cur];

        float xnext = 0.f;
        const bool pf = (tid < BTN) && (t + 1 < T_STEPS);
        if (pf) xnext = xg[(DEC ? t : t + 1) * BATCH + b0 + tid];

        // ---- fused gate + update over this group's batch rows ----
        for (int b = 0; b < bcnt; b++) {
            const int bb = bofs + b;
            const ulonglong2* hp = (const ulonglong2*)(hc + bb * HP);
            u64 a0 = 0ull, a1 = 0ull, a2 = 0ull, a3 = 0ull;
#pragma unroll
            for (int q = 0; q < 16; q++) {
                ulonglong2 h2 = hp[q];          // warp-uniform broadcast
                ffma2(a0, wa[2 * q],     h2.x, a0);
                ffma2(a1, wa[2 * q + 1], h2.y, a1);
                ffma2(a2, wb[2 * q],     h2.x, a2);
                ffma2(a3, wb[2 * q + 1], h2.y, a3);
            }
            float2 v0 = unpack2(a0), v1 = unpack2(a1);
            float2 v2 = unpack2(a2), v3 = unpack2(a3);
            float p0 = (v0.x + v0.y) + (v1.x + v1.y);   // row r0 (i or g)
            float p1 = (v2.x + v2.y) + (v3.x + v3.y);   // row r1 (f or o)
            const float x = xs[bb];
            p0 += bias0 + wih0 * x;
            p1 += bias1 + wih1 * x;
            if constexpr (H == 65) {
                const float h64 = hc[bb * HP + 64];
                p0 = fmaf(wrem_a, h64, p0);
                p1 = fmaf(wrem_b, h64, p1);
            }
            // A: sig(i), sig(f).  B: tanh(g), sig(o).
            const float a0v = act(p0, !isA);
            const float a1v = sigf(p1);
            const float og = __shfl_xor_sync(0xffffffffu, a0v, 16);  // A <- tanh(g)
            const float oo = __shfl_xor_sync(0xffffffffu, a1v, 16);  // A <- sig(o)
            if (isA) {
                const float cn = a1v * c[b] + a0v * og;
                c[b] = cn;
                hn[bb * HP + u] = oo * tanh_s(cn);
            }
        }

        // ---- decoder tasks: unit-64 gate+update, projection(t-1) ----
        if constexpr (DEC) {
#pragma unroll
            for (int k = 0; k < 2; k++) {
                const int b = w4 + 4 * k;
                if (b < bcnt) {
                    const int bb = bofs + b;
                    const float* hr = hc + bb * HP;
                    const float hv0 = hr[lane], hv1 = hr[lane + 32];
                    const float h64v = hr[64];
                    float ga[4];
#pragma unroll
                    for (int e = 0; e < 4; e++) {
                        float p = te0[e] * hv0 + te1[e] * hv1;
#pragma unroll
                        for (int off = 16; off; off >>= 1)
                            p += __shfl_down_sync(0xffffffffu, p, off);
                        ga[e] = p;              // lane 0 holds the sum
                    }
                    if (lane == 0) {
#pragma unroll
                        for (int e = 0; e < 4; e++) {
                            float g = ga[e] + te64[e] * h64v
                                    + sm.xbias[e] + sm.xwih[e] * xs[bb];
                            ga[e] = act(g, e == 2);
                        }
                        const float cn = ga[1] * c64r[k] + ga[0] * ga[2];
                        c64r[k] = cn;
                        hn[bb * HP + 64] = ga[3] * tanh_s(cn);
                    }
                    if (t > 0) {                // projection of state t-1
                        float p = lw0 * hv0 + lw1 * hv1;
#pragma unroll
                        for (int off = 16; off; off >>= 1)
                            p += __shfl_down_sync(0xffffffffu, p, off);
                        if (lane == 0)
                            out[(t - 1) * BATCH + b0 + bb] = p + lw64 * h64v + linb;
                    }
                }
            }
        }

        if (pf) sm.xbuf[cur ^ 1][tid] = xnext;
        __syncthreads();
        cur ^= 1;
    }

    // ---- decoder: final projection (state T-1, buffer cur) ----
    if constexpr (DEC) {
#pragma unroll
        for (int k = 0; k < 2; k++) {
            const int b = w4 + 4 * k;
            if (b < bcnt) {
                const int bb = bofs + b;
                const float* hr = sm.h[cur] + bb * HP;
                float p = lw0 * hr[lane] + lw1 * hr[lane + 32];
#pragma unroll
                for (int off = 16; off; off >>= 1)
                    p += __shfl_down_sync(0xffffffffu, p, off);
                if (lane == 0)
                    out[(T_STEPS - 1) * BATCH + b0 + bb] = p + lw64 * hr[64] + linb;
            }
        }
    }
}

template <int BTN>
__device__ void body(
    Smem& sm, int b0,
    const float* input, const float* speed, const float* target,
    const float* eWih, const float* eWhh, const float* ebih, const float* ebhh,
    const float* dWih, const float* dWhh, const float* dbih, const float* dbhh,
    const float* linb, const float* denseW, const float* denseb,
    float* out)
{
    const int tid = threadIdx.x;

    float c[7];
#pragma unroll
    for (int i = 0; i < 7; i++) c[i] = 0.f;

    // encoder (H=64): 1000 flips -> final h lands in buffer 0
    lstm_scan<64, false, BTN>(sm, b0, input, eWih, eWhh, ebih, ebhh,
                              c, 0.0f, nullptr);

    // transition: h64 = c64 = Dense(speed); teacher-forcing x0 = 0
    if (tid < BTN) {
        const float sp = denseb[0] + denseW[0] * speed[b0 + tid];
        sm.h[0][tid * HP + 64] = sp;
        sm.xbuf[0][tid] = 0.f;
    }
    __syncthreads();

    // decoder (H=65) + projection
    lstm_scan<65, true, BTN>(sm, b0, target, dWih, dWhh, dbih, dbhh,
                             c, linb[0], out);
}

__global__ void __launch_bounds__(NTHREADS, 1)
lstm_seq2seq_kernel(
    const float* __restrict__ input,  const float* __restrict__ speed,
    const float* __restrict__ target,
    const float* __restrict__ eWih,   const float* __restrict__ eWhh,
    const float* __restrict__ ebih,   const float* __restrict__ ebhh,
    const float* __restrict__ dWih,   const float* __restrict__ dWhh,
    const float* __restrict__ dbih,   const float* __restrict__ dbhh,
    const float* __restrict__ linW,   const float* __restrict__ linb,
    const float* __restrict__ denseW, const float* __restrict__ denseb,
    float* __restrict__ out)
{
    __shared__ Smem sm;
    const int tid  = threadIdx.x;
    const int cta  = blockIdx.x;
    const int base = BATCH / NCTA;     // 13
    const int rem  = BATCH % NCTA;     // 124
    const int bt   = base + (cta < rem ? 1 : 0);
    const int b0   = cta * base + min(cta, rem);

    for (int i = tid; i < 2 * BT_MAX * HP; i += NTHREADS)
        ((float*)sm.h)[i] = 0.f;
    // decoder unit-64 gate rows: global rows 65e + 64 (i,f,g,o)
    for (int i = tid; i < 4 * 65; i += NTHREADS) {
        const int e = i / 65, k2 = i - e * 65;
        sm.xw[e][k2] = dWhh[(65 * e + 64) * 65 + k2];
    }
    if (tid < 4) {
        const int r = 65 * tid + 64;
        sm.xwih[tid]  = dWih[r];
        sm.xbias[tid] = dbih[r] + dbhh[r];
    }
    for (int i = tid; i < 65; i += NTHREADS) sm.linW[i] = linW[i];
    if (tid < bt) sm.xbuf[0][tid] = input[b0 + tid];
    __syncthreads();

    if (bt == 14)
        body<14>(sm, b0, input, speed, target, eWih, eWhh, ebih, ebhh,
                 dWih, dWhh, dbih, dbhh, linb, denseW, denseb, out);
    else
        body<13>(sm, b0, input, speed, target, eWih, eWhh, ebih, ebhh,
                 dWih, dWhh, dbih, dbhh, linb, denseW, denseb, out);
}

extern "C" void kernel_launch(void* const* d_in, const int* in_sizes, int n_in,
                              void* d_out, int out_size)
{
    const float* input  = (const float*)d_in[0];
    const float* speed  = (const float*)d_in[1];
    const float* target = (const float*)d_in[2];
    const float* eWih   = (const float*)d_in[3];
    const float* eWhh   = (const float*)d_in[4];
    const float* ebih   = (const float*)d_in[5];
    const float* ebhh   = (const float*)d_in[6];
    const float* dWih   = (const float*)d_in[7];
    const float* dWhh   = (const float*)d_in[8];
    const float* dbih   = (const float*)d_in[9];
    const float* dbhh   = (const float*)d_in[10];
    const float* linW   = (const float*)d_in[11];
    const float* linb   = (const float*)d_in[12];
    const float* denseW = (const float*)d_in[13];
    const float* denseb = (const float*)d_in[14];
    float* out = (float*)d_out;

    lstm_seq2seq_kernel<<<NCTA, NTHREADS>>>(
        input, speed, target,
        eWih, eWhh, ebih, ebhh,
        dWih, dWhh, dbih, dbhh,
        linW, linb, denseW, denseb, out);
}